// round 16
// baseline (speedup 1.0000x reference)
#include <cuda_runtime.h>
#include <cuda_bf16.h>
#include <math.h>
#include <float.h>
#include <string.h>
#include <stdint.h>

#define KNN_K 32
typedef __nv_bfloat16 bf16;

// ---------------- scratch ----------------
__device__ __align__(16) float g_q[2048*2048];
__device__ __align__(16) float g_scores[2048*4096];
__device__ __align__(16) bf16 g_wv2[2][1024*512];
__device__ __align__(16) bf16 g_h2[2][2048*512];
__device__ __align__(16) float g_gate[2048*512];

// ---------------- helpers ----------------
__device__ __forceinline__ uint32_t smem_u32(const void* p){ return (uint32_t)__cvta_generic_to_shared(p); }
__device__ __forceinline__ void cp16(uint32_t dst, const void* src){
    asm volatile("cp.async.cg.shared.global [%0], [%1], 16;\n" :: "r"(dst), "l"(src));
}
__device__ __forceinline__ void cp_commit(){ asm volatile("cp.async.commit_group;\n" ::: "memory"); }
template<int N> __device__ __forceinline__ void cp_wait(){ asm volatile("cp.async.wait_group %0;\n" :: "n"(N) : "memory"); }
__device__ __forceinline__ void ldsm4(uint32_t (&r)[4], uint32_t addr){
    asm volatile("ldmatrix.sync.aligned.m8n8.x4.shared.b16 {%0,%1,%2,%3}, [%4];"
        : "=r"(r[0]), "=r"(r[1]), "=r"(r[2]), "=r"(r[3]) : "r"(addr));
}
__device__ __forceinline__ void mma16816(float (&d)[4], const uint32_t (&a)[4], uint32_t b0, uint32_t b1){
    asm volatile("mma.sync.aligned.m16n8k16.row.col.f32.bf16.bf16.f32 "
        "{%0,%1,%2,%3}, {%4,%5,%6,%7}, {%8,%9}, {%0,%1,%2,%3};"
        : "+f"(d[0]), "+f"(d[1]), "+f"(d[2]), "+f"(d[3])
        : "r"(a[0]), "r"(a[1]), "r"(a[2]), "r"(a[3]), "r"(b0), "r"(b1));
}
__device__ __forceinline__ void ffma2(uint64_t& d, uint64_t a, uint64_t b){
    asm("fma.rn.f32x2 %0, %1, %2, %3;" : "=l"(d) : "l"(a), "l"(b), "l"(d));
}
__device__ __forceinline__ uint64_t pack2(float v){
    uint64_t d; asm("mov.b64 %0, {%1, %1};" : "=l"(d) : "f"(v)); return d;
}
__device__ __forceinline__ void split2v(float v, bf16& h, bf16& l){
    h = __float2bfloat16(v);
    l = __float2bfloat16(v - __bfloat162float(h));
}
// compare-exchange (descending) + Batcher odd-even sort-8
__device__ __forceinline__ void ce(unsigned long long& a, unsigned long long& b){
    if (a < b){ unsigned long long t = a; a = b; b = t; }
}
__device__ __forceinline__ void sort8_desc(unsigned long long (&k)[8]){
    ce(k[0],k[1]); ce(k[2],k[3]); ce(k[4],k[5]); ce(k[6],k[7]);
    ce(k[0],k[2]); ce(k[1],k[3]); ce(k[4],k[6]); ce(k[5],k[7]);
    ce(k[1],k[2]); ce(k[5],k[6]);
    ce(k[0],k[4]); ce(k[1],k[5]); ce(k[2],k[6]); ce(k[3],k[7]);
    ce(k[2],k[4]); ce(k[3],k[5]);
    ce(k[1],k[2]); ce(k[3],k[4]); ce(k[5],k[6]);
}

// ---------------- q-GEMM: fp32 f32x2, 128x256 tile, 512 thr (verbatim) ------
__global__ __launch_bounds__(512) void gemm_q(
    const float* __restrict__ A, const float* __restrict__ B,
    const float* __restrict__ bias, float* __restrict__ C)
{
    constexpr int BM = 128, BN = 256, BK = 16;
    const int K = 1024, lda = 1024, ldb = 2048, ldc = 2048;
    __shared__ float As[BK][BM];
    __shared__ float Bs[BK][BN];

    const int bm = blockIdx.y * BM, bn = blockIdx.x * BN;
    const int tid = threadIdx.x;
    const int lane = tid & 31, wid = tid >> 5;

    uint64_t acc2[4][8];
#pragma unroll
    for (int i = 0; i < 4; i++)
#pragma unroll
        for (int j = 0; j < 8; j++) acc2[i][j] = 0ull;

    const int ar = tid >> 2, ac = (tid & 3) * 4;
    float4 ra, rb0, rb1;
    auto ldg = [&](int k0){
        ra = *(const float4*)(A + (long)(bm + ar) * lda + k0 + ac);
        const int bk = tid >> 6, bc = (tid & 63) * 4;
        rb0 = *(const float4*)(B + (long)(k0 + bk) * ldb + bn + bc);
        rb1 = *(const float4*)(B + (long)(k0 + bk + 8) * ldb + bn + bc);
    };
    auto sts = [&](){
        As[ac + 0][ar] = ra.x; As[ac + 1][ar] = ra.y;
        As[ac + 2][ar] = ra.z; As[ac + 3][ar] = ra.w;
        const int bk = tid >> 6, bc = (tid & 63) * 4;
        *(float4*)&Bs[bk][bc]     = rb0;
        *(float4*)&Bs[bk + 8][bc] = rb1;
    };

    const int nch = K / BK;
    ldg(0);
    for (int c = 0; c < nch; c++){
        sts();
        __syncthreads();
        if (c + 1 < nch) ldg((c + 1) * BK);
#pragma unroll
        for (int kk = 0; kk < BK; kk++){
            uint64_t a2[4];
#pragma unroll
            for (int i = 0; i < 4; i++)
                a2[i] = *(const uint64_t*)&As[kk][wid * 8 + 2 * i];
            float4 b40 = *(const float4*)&Bs[kk][lane * 4];
            float4 b41 = *(const float4*)&Bs[kk][128 + lane * 4];
            uint64_t b2[8] = {pack2(b40.x), pack2(b40.y), pack2(b40.z), pack2(b40.w),
                              pack2(b41.x), pack2(b41.y), pack2(b41.z), pack2(b41.w)};
#pragma unroll
            for (int i = 0; i < 4; i++)
#pragma unroll
                for (int j = 0; j < 8; j++)
                    ffma2(acc2[i][j], a2[i], b2[j]);
        }
        __syncthreads();
    }

#pragma unroll
    for (int i = 0; i < 4; i++){
#pragma unroll
        for (int h2 = 0; h2 < 2; h2++){
            const int r = bm + wid * 8 + i * 2 + h2;
#pragma unroll
            for (int grp = 0; grp < 2; grp++){
                const int col = bn + grp * 128 + lane * 4;
                float4 o; float* po = &o.x;
#pragma unroll
                for (int u = 0; u < 4; u++){
                    float2 p; memcpy(&p, &acc2[i][grp * 4 + u], 8);
                    float v = h2 ? p.y : p.x;
                    v += bias[col + u];
                    po[u] = v;
                }
                *(float4*)(C + (long)r * ldc + col) = o;
            }
        }
    }
}

// ---------------- gate (z+zoff==0, silu) / scores (z+zoff>=1, BT) ----------------
// zoff=0 grid z=1 -> gate only (side stream); zoff=1 grid z=8 -> scores only
__global__ __launch_bounds__(512) void scores_gate_kernel(
    const float* __restrict__ qm, const float* __restrict__ keys,
    const float* __restrict__ x,  const float* __restrict__ Ws,
    const float* __restrict__ bs, float* __restrict__ scores, float* __restrict__ gate,
    int zoff)
{
    constexpr int BM = 128, BN = 256, BK = 16;
    __shared__ float As[BK][BM];
    __shared__ float Bs[BK][BN];

    const int  z   = blockIdx.z + zoff;
    const bool isg = (z == 0);
    const int  zb  = z - 1;
    const float* A = isg ? x    : qm   + (long)zb * 256;
    const float* B = isg ? Ws   : keys + (long)zb * 512 * 256;
    float*       C = isg ? gate : scores + (long)zb * 512;
    const int K   = isg ? 1024 : 256;
    const int lda = isg ? 1024 : 2048;
    const int ldb = isg ? 512  : 256;
    const int ldc = isg ? 512  : 4096;
    const bool bt = !isg;

    const int bm = blockIdx.y * BM, bn = blockIdx.x * BN;
    const int tid = threadIdx.x;
    const int lane = tid & 31, wid = tid >> 5;

    uint64_t acc2[4][8];
#pragma unroll
    for (int i = 0; i < 4; i++)
#pragma unroll
        for (int j = 0; j < 8; j++) acc2[i][j] = 0ull;

    const int ar = tid >> 2, ac = (tid & 3) * 4;
    float4 ra, rb0, rb1;
    auto ldg = [&](int k0){
        ra = *(const float4*)(A + (long)(bm + ar) * lda + k0 + ac);
        if (bt){
            rb0 = *(const float4*)(B + (long)(bn + ar) * ldb + k0 + ac);
            rb1 = *(const float4*)(B + (long)(bn + ar + 128) * ldb + k0 + ac);
        } else {
            const int bk = tid >> 6, bc = (tid & 63) * 4;
            rb0 = *(const float4*)(B + (long)(k0 + bk) * ldb + bn + bc);
            rb1 = *(const float4*)(B + (long)(k0 + bk + 8) * ldb + bn + bc);
        }
    };
    auto sts = [&](){
        As[ac + 0][ar] = ra.x; As[ac + 1][ar] = ra.y;
        As[ac + 2][ar] = ra.z; As[ac + 3][ar] = ra.w;
        if (bt){
            Bs[ac + 0][ar] = rb0.x; Bs[ac + 1][ar] = rb0.y;
            Bs[ac + 2][ar] = rb0.z; Bs[ac + 3][ar] = rb0.w;
            Bs[ac + 0][ar + 128] = rb1.x; Bs[ac + 1][ar + 128] = rb1.y;
            Bs[ac + 2][ar + 128] = rb1.z; Bs[ac + 3][ar + 128] = rb1.w;
        } else {
            const int bk = tid >> 6, bc = (tid & 63) * 4;
            *(float4*)&Bs[bk][bc]     = rb0;
            *(float4*)&Bs[bk + 8][bc] = rb1;
        }
    };

    const int nch = K / BK;
    ldg(0);
    for (int c = 0; c < nch; c++){
        sts();
        __syncthreads();
        if (c + 1 < nch) ldg((c + 1) * BK);
#pragma unroll
        for (int kk = 0; kk < BK; kk++){
            uint64_t a2[4];
#pragma unroll
            for (int i = 0; i < 4; i++)
                a2[i] = *(const uint64_t*)&As[kk][wid * 8 + 2 * i];
            float4 b40 = *(const float4*)&Bs[kk][lane * 4];
            float4 b41 = *(const float4*)&Bs[kk][128 + lane * 4];
            uint64_t b2[8] = {pack2(b40.x), pack2(b40.y), pack2(b40.z), pack2(b40.w),
                              pack2(b41.x), pack2(b41.y), pack2(b41.z), pack2(b41.w)};
#pragma unroll
            for (int i = 0; i < 4; i++)
#pragma unroll
                for (int j = 0; j < 8; j++)
                    ffma2(acc2[i][j], a2[i], b2[j]);
        }
        __syncthreads();
    }

#pragma unroll
    for (int i = 0; i < 4; i++){
#pragma unroll
        for (int h2 = 0; h2 < 2; h2++){
            const int r = bm + wid * 8 + i * 2 + h2;
#pragma unroll
            for (int grp = 0; grp < 2; grp++){
                const int col = bn + grp * 128 + lane * 4;
                float4 o; float* po = &o.x;
#pragma unroll
                for (int u = 0; u < 4; u++){
                    float2 p; memcpy(&p, &acc2[i][grp * 4 + u], 8);
                    float v = h2 ? p.y : p.x;
                    if (isg){ v += bs[col + u]; v = v / (1.0f + expf(-v)); }
                    po[u] = v;
                }
                *(float4*)(C + (long)r * ldc + col) = o;
            }
        }
    }
}

// ---------------- HMMA 2-split out-GEMM (verbatim) ----------------
__global__ __launch_bounds__(256, 1) void gemm_mma_out(
    const bf16* __restrict__ A0, const bf16* __restrict__ A1,
    const bf16* __restrict__ B0, const bf16* __restrict__ B1,
    const float* __restrict__ bias, float* __restrict__ C,
    int K, int lda, int ldb, int ldc)
{
    extern __shared__ char dsm[];
    const int tid = threadIdx.x, wid = tid >> 5, lane = tid & 31;
    const int wm = wid & 1, wn = wid >> 1;
    const int bm = blockIdx.y * 128, bn = blockIdx.x * 128;
    const bf16* As[2] = {A0, A1};
    const bf16* Bs[2] = {B0, B1};

    uint32_t sb = (smem_u32(dsm) + 1023u) & ~1023u;
    const int nch = K >> 6;

    auto load_tile = [&](uint32_t st, const bf16* g, int ld, int c0){
#pragma unroll
        for (int t = 0; t < 4; t++){
            int c = tid + t * 256, r = c >> 3, c8 = c & 7;
            cp16(st + (uint32_t)(r * 128) + (uint32_t)(((c8 ^ (r & 7)) * 16)),
                 g + (size_t)r * ld + c0 + c8 * 8);
        }
    };
    auto load_chunk = [&](int stage, int k0){
        uint32_t st = sb + stage * 65536u;
#pragma unroll
        for (int sp = 0; sp < 2; sp++) load_tile(st + sp * 16384, As[sp] + (size_t)bm * lda, lda, k0);
#pragma unroll
        for (int sp = 0; sp < 2; sp++) load_tile(st + (2 + sp) * 16384, Bs[sp] + (size_t)bn * ldb, ldb, k0);
        cp_commit();
    };

    float acc[4][4][4];
#pragma unroll
    for (int i = 0; i < 4; i++)
#pragma unroll
        for (int j = 0; j < 4; j++)
#pragma unroll
            for (int u = 0; u < 4; u++) acc[i][j][u] = 0.0f;

    const int lr = lane & 15, lk = lane >> 4;

    load_chunk(0, 0);
    for (int c = 0; c < nch; c++){
        const int s = c & 1;
        if (c + 1 < nch){ load_chunk((c + 1) & 1, (c + 1) << 6); cp_wait<1>(); }
        else cp_wait<0>();
        __syncthreads();

        const uint32_t stg = sb + s * 65536u;
#pragma unroll
        for (int ks = 0; ks < 4; ks++){
            const int kc = ks * 2 + lk;
            uint32_t af[2][4][4], bfr[2][2][4];
#pragma unroll
            for (int sp = 0; sp < 2; sp++)
#pragma unroll
                for (int i = 0; i < 4; i++){
                    int r = wm * 64 + i * 16 + lr;
                    ldsm4(af[sp][i], stg + sp * 16384 + (uint32_t)(r * 128) + (uint32_t)(((kc ^ (r & 7)) * 16)));
                }
#pragma unroll
            for (int sp = 0; sp < 2; sp++)
#pragma unroll
                for (int j2 = 0; j2 < 2; j2++){
                    int rn = wn * 32 + j2 * 16 + lr;
                    ldsm4(bfr[sp][j2], stg + (2 + sp) * 16384 + (uint32_t)(rn * 128) + (uint32_t)(((kc ^ (rn & 7)) * 16)));
                }
#pragma unroll
            for (int i = 0; i < 4; i++)
#pragma unroll
                for (int j2 = 0; j2 < 2; j2++){
                    mma16816(acc[i][2*j2],   af[0][i], bfr[0][j2][0], bfr[0][j2][2]);
                    mma16816(acc[i][2*j2+1], af[0][i], bfr[0][j2][1], bfr[0][j2][3]);
                    mma16816(acc[i][2*j2],   af[0][i], bfr[1][j2][0], bfr[1][j2][2]);
                    mma16816(acc[i][2*j2+1], af[0][i], bfr[1][j2][1], bfr[1][j2][3]);
                    mma16816(acc[i][2*j2],   af[1][i], bfr[0][j2][0], bfr[0][j2][2]);
                    mma16816(acc[i][2*j2+1], af[1][i], bfr[0][j2][1], bfr[0][j2][3]);
                }
        }
        __syncthreads();
    }

    const int tr = lane >> 2, tc = (lane & 3) * 2;
#pragma unroll
    for (int i = 0; i < 4; i++)
#pragma unroll
        for (int h2 = 0; h2 < 2; h2++){
            const int row = bm + wm * 64 + i * 16 + tr + h2 * 8;
#pragma unroll
            for (int j = 0; j < 4; j++){
                const int col = bn + wn * 32 + j * 8 + tc;
                float v0 = acc[i][j][h2*2] + bias[col];
                float v1 = acc[i][j][h2*2+1] + bias[col+1];
                *(float2*)(C + (size_t)row * ldc + col) = make_float2(v0, v1);
            }
        }
}

// ---------------- prep: Wv [K][N] -> wv2 splits [N][K] ----------------
__global__ void tsplit_kernel(const float* __restrict__ in,
    bf16* __restrict__ o0, bf16* __restrict__ o1, int K, int N)
{
    __shared__ float t[32][33];
    int k0 = blockIdx.y * 32, n0 = blockIdx.x * 32;
    t[threadIdx.y][threadIdx.x] = in[(size_t)(k0 + threadIdx.y) * N + n0 + threadIdx.x];
    __syncthreads();
    float v = t[threadIdx.x][threadIdx.y];
    size_t o = (size_t)(n0 + threadIdx.y) * K + k0 + threadIdx.x;
    bf16 h, l; split2v(v, h, l);
    o0[o] = h; o1[o] = l;
}

// ---------------- fused topk1(sorted-merge) + topk2 + gather ----------------
__constant__ unsigned short c_cand[128] = {
    0x000,0x001,0x002,0x003,0x004,0x005,0x006,0x007,0x008,0x009,0x00A,0x00B,0x00C,0x00D,0x00E,0x00F,
    0x010,0x011,0x012,0x013,0x014,0x015,0x016,0x017,0x018,0x019,0x01A,0x01B,0x01C,0x01D,0x01E,0x01F,
    0x100,0x101,0x102,0x103,0x104,0x105,0x106,0x107,0x108,0x109,0x10A,0x10B,0x10C,0x10D,0x10E,0x10F,
    0x200,0x201,0x202,0x203,0x204,0x205,0x206,0x207,0x208,0x209,
    0x300,0x301,0x302,0x303,0x304,0x305,0x306,0x307,
    0x400,0x401,0x402,0x403,0x404,0x405,
    0x500,0x501,0x502,0x503,0x504,
    0x600,0x601,0x602,0x603,
    0x700,0x701,0x702,0x703,
    0x800,0x801,0x802, 0x900,0x901,0x902,
    0xA00,0xA01, 0xB00,0xB01, 0xC00,0xC01, 0xD00,0xD01, 0xE00,0xE01, 0xF00,0xF01,
    0x1000,0x1100,0x1200,0x1300,0x1400,0x1500,0x1600,0x1700,
    0x1800,0x1900,0x1A00,0x1B00,0x1C00,0x1D00,0x1E00,0x1F00,
    0xFFFF,0xFFFF,0xFFFF,0xFFFF,0xFFFF,0xFFFF,0xFFFF,0xFFFF,0xFFFF };

__global__ __launch_bounds__(256) void topk_gather_kernel(const float* __restrict__ values)
{
    const int n = blockIdx.x;
    const int tid = threadIdx.x;
    const int wid = tid >> 5, lane = tid & 31;
    const unsigned FULL = 0xffffffffu;

    __shared__ float s_ts[8][32];
    __shared__ int   s_ti[8][32];
    __shared__ unsigned long long s_lists[8][16][32];
    __shared__ unsigned long long skeys[4][128];
    __shared__ float s_cw[128];
    __shared__ int   s_ci[128];

    // ---- stage 1: sorted 8-lists + 32-pop merge with REDUX argmax ----
    {
        const float* sc = g_scores + (size_t)n * 4096 + (size_t)wid * 512;
        unsigned long long kA[8], kB[8];
#pragma unroll
        for (int i = 0; i < 8; i++){
            float v = sc[i * 32 + lane];
            unsigned u = __float_as_uint(v);
            unsigned s = (u & 0x80000000u) ? ~u : (u | 0x80000000u);
            kA[i] = ((unsigned long long)s << 32) | (unsigned long long)(1023 - (i * 32 + lane));
        }
#pragma unroll
        for (int i = 0; i < 8; i++){
            float v = sc[(i + 8) * 32 + lane];
            unsigned u = __float_as_uint(v);
            unsigned s = (u & 0x80000000u) ? ~u : (u | 0x80000000u);
            kB[i] = ((unsigned long long)s << 32) | (unsigned long long)(1023 - ((i + 8) * 32 + lane));
        }
        sort8_desc(kA);
        sort8_desc(kB);
#pragma unroll
        for (int i = 0; i < 8; i++){
            s_lists[wid][i][lane]     = kA[i];
            s_lists[wid][8 + i][lane] = kB[i];
        }
        __syncwarp();

        int pA = 1, pB = 1;
        unsigned long long hA = kA[0], hB = kB[0];
        unsigned long long out = 0ull;
        for (int it = 0; it < 32; it++){
            unsigned long long h = (hA > hB) ? hA : hB;
            unsigned hi = (unsigned)(h >> 32);
            unsigned mhi = __reduce_max_sync(FULL, hi);
            unsigned lo = (hi == mhi) ? (unsigned)(h & 1023ull) : 0u;
            unsigned mlo = __reduce_max_sync(FULL, lo);
            unsigned long long m = ((unsigned long long)mhi << 32) | (unsigned long long)mlo;
            if (lane == it) out = m;
            if (h == m){
                if (hA == m){ hA = (pA < 8) ? s_lists[wid][pA][lane] : 0ull; pA++; }
                else        { hB = (pB < 8) ? s_lists[wid][8 + pB][lane] : 0ull; pB++; }
            }
        }
        unsigned sv = (unsigned)(out >> 32);
        unsigned ub = (sv & 0x80000000u) ? (sv & 0x7FFFFFFFu) : ~sv;
        s_ts[wid][lane] = __uint_as_float(ub);
        s_ti[wid][lane] = 1023 - (int)(out & 1023ull);
    }
    __syncthreads();

    // ---- stage 2: warps 0-3, dominance pruning + counting selection + softmax ----
    if (wid < 4){
        const int h = wid;
        float s1 = s_ts[h * 2][lane];
        float s2 = s_ts[h * 2 + 1][lane];

        float val[4]; unsigned long long key[4]; int ci_[4], cj_[4]; bool real[4];
#pragma unroll
        for (int s = 0; s < 4; s++){
            unsigned pk = c_cand[lane * 4 + s];
            int ci = (pk >> 8) & 31, cj = pk & 31;
            ci_[s] = ci; cj_[s] = cj;
            real[s] = (pk != 0xFFFFu);
            float v = __shfl_sync(FULL, s1, ci) + __shfl_sync(FULL, s2, cj);
            val[s] = v;
            unsigned u = __float_as_uint(v);
            unsigned sv = (u & 0x80000000u) ? ~u : (u | 0x80000000u);
            unsigned p = (unsigned)(ci * 32 + cj);
            key[s] = real[s] ? (((unsigned long long)sv << 32) | (unsigned long long)(1023u - p)) : 0ull;
            skeys[h][lane * 4 + s] = key[s];
        }
        __syncwarp();

        int cnt[4] = {0,0,0,0};
        for (int k2 = 0; k2 < 128; k2++){
            unsigned long long o = skeys[h][k2];
#pragma unroll
            for (int s = 0; s < 4; s++) cnt[s] += (o > key[s]);
        }
        bool sel[4];
#pragma unroll
        for (int s = 0; s < 4; s++) sel[s] = real[s] && (cnt[s] < 32);

        float m = -FLT_MAX;
#pragma unroll
        for (int s = 0; s < 4; s++) if (sel[s] && val[s] > m) m = val[s];
#pragma unroll
        for (int off = 16; off; off >>= 1) m = fmaxf(m, __shfl_xor_sync(FULL, m, off));
        float e[4], sum = 0.0f;
#pragma unroll
        for (int s = 0; s < 4; s++){ e[s] = sel[s] ? expf(val[s] - m) : 0.0f; sum += e[s]; }
#pragma unroll
        for (int off = 16; off; off >>= 1) sum += __shfl_xor_sync(FULL, sum, off);

#pragma unroll
        for (int s = 0; s < 4; s++){
            if (sel[s]){
                s_cw[h * 32 + cnt[s]] = e[s] / sum;
                s_ci[h * 32 + cnt[s]] = s_ti[h * 2][ci_[s]] * 512 + s_ti[h * 2 + 1][cj_[s]];
            }
        }
    }
    __syncthreads();

    // ---- gather: 256 threads, float2 over 512 dims, 4 indep chains (MLP x4) ----
    float2 a0 = {0.f,0.f}, a1 = {0.f,0.f}, a2c = {0.f,0.f}, a3 = {0.f,0.f};
#pragma unroll 2
    for (int r = 0; r < 128; r += 4){
        float w0 = s_cw[r],     w1 = s_cw[r + 1];
        float w2 = s_cw[r + 2], w3 = s_cw[r + 3];
        const float2 v0 = *((const float2*)(values + (size_t)s_ci[r]     * 512) + tid);
        const float2 v1 = *((const float2*)(values + (size_t)s_ci[r + 1] * 512) + tid);
        const float2 v2 = *((const float2*)(values + (size_t)s_ci[r + 2] * 512) + tid);
        const float2 v3 = *((const float2*)(values + (size_t)s_ci[r + 3] * 512) + tid);
        a0.x += w0 * v0.x; a0.y += w0 * v0.y;
        a1.x += w1 * v1.x; a1.y += w1 * v1.y;
        a2c.x += w2 * v2.x; a2c.y += w2 * v2.y;
        a3.x += w3 * v3.x; a3.y += w3 * v3.y;
    }
    float2 g = *((const float2*)(g_gate + (size_t)n * 512) + tid);
    float o0 = ((a0.x + a1.x) + (a2c.x + a3.x)) * g.x;
    float o1 = ((a0.y + a1.y) + (a2c.y + a3.y)) * g.y;
    bf16 h0,l0,h1,l1;
    split2v(o0,h0,l0); split2v(o1,h1,l1);
    *(uint32_t*)(&g_h2[0][(size_t)n * 512 + tid * 2]) =
        (uint32_t)__bfloat16_as_ushort(h0) | ((uint32_t)__bfloat16_as_ushort(h1) << 16);
    *(uint32_t*)(&g_h2[1][(size_t)n * 512 + tid * 2]) =
        (uint32_t)__bfloat16_as_ushort(l0) | ((uint32_t)__bfloat16_as_ushort(l1) << 16);
}

// ---------------- launch ----------------
extern "C" void kernel_launch(void* const* d_in, const int* in_sizes, int n_in,
                              void* d_out, int out_size)
{
    const float* x      = (const float*)d_in[0];
    const float* Wq     = (const float*)d_in[1];
    const float* bq     = (const float*)d_in[2];
    const float* keys   = (const float*)d_in[3];
    const float* values = (const float*)d_in[4];
    const float* Ws     = (const float*)d_in[5];
    const float* bs     = (const float*)d_in[6];
    const float* Wv     = (const float*)d_in[7];
    const float* bv     = (const float*)d_in[8];
    float* out          = (float*)d_out;

    static cudaStream_t s2 = nullptr;
    static cudaEvent_t e1 = nullptr, e2 = nullptr;
    if (!s2){
        cudaStreamCreateWithFlags(&s2, cudaStreamNonBlocking);
        cudaEventCreateWithFlags(&e1, cudaEventDisableTiming);
        cudaEventCreateWithFlags(&e2, cudaEventDisableTiming);
        const int SMEM2 = 2 * 2 * 32768;
        cudaFuncSetAttribute(gemm_mma_out, cudaFuncAttributeMaxDynamicSharedMemorySize, SMEM2);
    }
    const int SMEM2 = 2 * 2 * 32768;

    float *q, *scores, *gate;
    bf16 *wv2[2], *h2[2];
    cudaGetSymbolAddress((void**)&q, g_q);
    cudaGetSymbolAddress((void**)&scores, g_scores);
    cudaGetSymbolAddress((void**)&gate, g_gate);
    {
        bf16* base;
        cudaGetSymbolAddress((void**)&base, g_wv2); for (int i=0;i<2;i++) wv2[i] = base + (size_t)i*1024*512;
        cudaGetSymbolAddress((void**)&base, g_h2);  for (int i=0;i<2;i++) h2[i]  = base + (size_t)i*2048*512;
    }

    // fork: gate + tsplit on side stream, overlapping q-GEMM
    cudaEventRecord(e1, 0);
    cudaStreamWaitEvent(s2, e1, 0);
    scores_gate_kernel<<<dim3(2, 16, 1), 512, 0, s2>>>(q, keys, x, Ws, bs, scores, gate, 0);
    tsplit_kernel<<<dim3(32, 16), dim3(32, 32), 0, s2>>>(Wv, wv2[0], wv2[1], 512, 1024);
    cudaEventRecord(e2, s2);

    // main stream: q then scores
    gemm_q<<<dim3(2048/256, 2048/128, 1), 512>>>(x, Wq, bq, q);
    scores_gate_kernel<<<dim3(2, 16, 8), 512>>>(q, keys, x, Ws, bs, scores, gate, 1);

    // join: topk_gather needs gate; out-GEMM needs tsplit
    cudaStreamWaitEvent(0, e2, 0);
    topk_gather_kernel<<<2048, 256>>>(values);
    gemm_mma_out<<<dim3(8,16,1), 256, SMEM2>>>(
        h2[0], h2[1], wv2[0], wv2[1], bv, out, 512, 512, 512, 1024);
}

// round 17
// speedup vs baseline: 1.1854x; 1.1854x over previous
#include <cuda_runtime.h>
#include <cuda_bf16.h>
#include <math.h>
#include <float.h>
#include <string.h>
#include <stdint.h>

#define KNN_K 32
typedef __nv_bfloat16 bf16;

// ---------------- scratch ----------------
__device__ __align__(16) float g_q[2048*2048];
__device__ __align__(16) float g_scores[2048*4096];
__device__ __align__(16) bf16 g_wv2[2][1024*512];
__device__ __align__(16) bf16 g_h2[2][2048*512];
__device__ __align__(16) float g_gate[2048*512];

// ---------------- helpers ----------------
__device__ __forceinline__ uint32_t smem_u32(const void* p){ return (uint32_t)__cvta_generic_to_shared(p); }
__device__ __forceinline__ void cp16(uint32_t dst, const void* src){
    asm volatile("cp.async.cg.shared.global [%0], [%1], 16;\n" :: "r"(dst), "l"(src));
}
__device__ __forceinline__ void cp_commit(){ asm volatile("cp.async.commit_group;\n" ::: "memory"); }
template<int N> __device__ __forceinline__ void cp_wait(){ asm volatile("cp.async.wait_group %0;\n" :: "n"(N) : "memory"); }
__device__ __forceinline__ void ldsm4(uint32_t (&r)[4], uint32_t addr){
    asm volatile("ldmatrix.sync.aligned.m8n8.x4.shared.b16 {%0,%1,%2,%3}, [%4];"
        : "=r"(r[0]), "=r"(r[1]), "=r"(r[2]), "=r"(r[3]) : "r"(addr));
}
__device__ __forceinline__ void mma16816(float (&d)[4], const uint32_t (&a)[4], uint32_t b0, uint32_t b1){
    asm volatile("mma.sync.aligned.m16n8k16.row.col.f32.bf16.bf16.f32 "
        "{%0,%1,%2,%3}, {%4,%5,%6,%7}, {%8,%9}, {%0,%1,%2,%3};"
        : "+f"(d[0]), "+f"(d[1]), "+f"(d[2]), "+f"(d[3])
        : "r"(a[0]), "r"(a[1]), "r"(a[2]), "r"(a[3]), "r"(b0), "r"(b1));
}
__device__ __forceinline__ void ffma2(uint64_t& d, uint64_t a, uint64_t b){
    asm("fma.rn.f32x2 %0, %1, %2, %3;" : "=l"(d) : "l"(a), "l"(b), "l"(d));
}
__device__ __forceinline__ uint64_t pack2(float v){
    uint64_t d; asm("mov.b64 %0, {%1, %1};" : "=l"(d) : "f"(v)); return d;
}
__device__ __forceinline__ void split2v(float v, bf16& h, bf16& l){
    h = __float2bfloat16(v);
    l = __float2bfloat16(v - __bfloat162float(h));
}
// compare-exchange (descending) + Batcher odd-even sort-8
__device__ __forceinline__ void ce(unsigned long long& a, unsigned long long& b){
    if (a < b){ unsigned long long t = a; a = b; b = t; }
}
__device__ __forceinline__ void sort8_desc(unsigned long long (&k)[8]){
    ce(k[0],k[1]); ce(k[2],k[3]); ce(k[4],k[5]); ce(k[6],k[7]);
    ce(k[0],k[2]); ce(k[1],k[3]); ce(k[4],k[6]); ce(k[5],k[7]);
    ce(k[1],k[2]); ce(k[5],k[6]);
    ce(k[0],k[4]); ce(k[1],k[5]); ce(k[2],k[6]); ce(k[3],k[7]);
    ce(k[2],k[4]); ce(k[3],k[5]);
    ce(k[1],k[2]); ce(k[3],k[4]); ce(k[5],k[6]);
}

// ---------------- q-GEMM: fp32 f32x2, 128x256 tile, 512 thr (verbatim R15) ------
__global__ __launch_bounds__(512) void gemm_q(
    const float* __restrict__ A, const float* __restrict__ B,
    const float* __restrict__ bias, float* __restrict__ C)
{
    constexpr int BM = 128, BN = 256, BK = 16;
    const int K = 1024, lda = 1024, ldb = 2048, ldc = 2048;
    __shared__ float As[BK][BM];
    __shared__ float Bs[BK][BN];

    const int bm = blockIdx.y * BM, bn = blockIdx.x * BN;
    const int tid = threadIdx.x;
    const int lane = tid & 31, wid = tid >> 5;

    uint64_t acc2[4][8];
#pragma unroll
    for (int i = 0; i < 4; i++)
#pragma unroll
        for (int j = 0; j < 8; j++) acc2[i][j] = 0ull;

    const int ar = tid >> 2, ac = (tid & 3) * 4;
    float4 ra, rb0, rb1;
    auto ldg = [&](int k0){
        ra = *(const float4*)(A + (long)(bm + ar) * lda + k0 + ac);
        const int bk = tid >> 6, bc = (tid & 63) * 4;
        rb0 = *(const float4*)(B + (long)(k0 + bk) * ldb + bn + bc);
        rb1 = *(const float4*)(B + (long)(k0 + bk + 8) * ldb + bn + bc);
    };
    auto sts = [&](){
        As[ac + 0][ar] = ra.x; As[ac + 1][ar] = ra.y;
        As[ac + 2][ar] = ra.z; As[ac + 3][ar] = ra.w;
        const int bk = tid >> 6, bc = (tid & 63) * 4;
        *(float4*)&Bs[bk][bc]     = rb0;
        *(float4*)&Bs[bk + 8][bc] = rb1;
    };

    const int nch = K / BK;
    ldg(0);
    for (int c = 0; c < nch; c++){
        sts();
        __syncthreads();
        if (c + 1 < nch) ldg((c + 1) * BK);
#pragma unroll
        for (int kk = 0; kk < BK; kk++){
            uint64_t a2[4];
#pragma unroll
            for (int i = 0; i < 4; i++)
                a2[i] = *(const uint64_t*)&As[kk][wid * 8 + 2 * i];
            float4 b40 = *(const float4*)&Bs[kk][lane * 4];
            float4 b41 = *(const float4*)&Bs[kk][128 + lane * 4];
            uint64_t b2[8] = {pack2(b40.x), pack2(b40.y), pack2(b40.z), pack2(b40.w),
                              pack2(b41.x), pack2(b41.y), pack2(b41.z), pack2(b41.w)};
#pragma unroll
            for (int i = 0; i < 4; i++)
#pragma unroll
                for (int j = 0; j < 8; j++)
                    ffma2(acc2[i][j], a2[i], b2[j]);
        }
        __syncthreads();
    }

#pragma unroll
    for (int i = 0; i < 4; i++){
#pragma unroll
        for (int h2 = 0; h2 < 2; h2++){
            const int r = bm + wid * 8 + i * 2 + h2;
#pragma unroll
            for (int grp = 0; grp < 2; grp++){
                const int col = bn + grp * 128 + lane * 4;
                float4 o; float* po = &o.x;
#pragma unroll
                for (int u = 0; u < 4; u++){
                    float2 p; memcpy(&p, &acc2[i][grp * 4 + u], 8);
                    float v = h2 ? p.y : p.x;
                    v += bias[col + u];
                    po[u] = v;
                }
                *(float4*)(C + (long)r * ldc + col) = o;
            }
        }
    }
}

// ---------------- fused gate (z=0, silu) + scores (z=1..8, BT) (verbatim R15) ----
__global__ __launch_bounds__(512) void scores_gate_kernel(
    const float* __restrict__ qm, const float* __restrict__ keys,
    const float* __restrict__ x,  const float* __restrict__ Ws,
    const float* __restrict__ bs, float* __restrict__ scores, float* __restrict__ gate)
{
    constexpr int BM = 128, BN = 256, BK = 16;
    __shared__ float As[BK][BM];
    __shared__ float Bs[BK][BN];

    const bool isg = (blockIdx.z == 0);
    const int  zb  = blockIdx.z - 1;
    const float* A = isg ? x    : qm   + (long)zb * 256;
    const float* B = isg ? Ws   : keys + (long)zb * 512 * 256;
    float*       C = isg ? gate : scores + (long)zb * 512;
    const int K   = isg ? 1024 : 256;
    const int lda = isg ? 1024 : 2048;
    const int ldb = isg ? 512  : 256;
    const int ldc = isg ? 512  : 4096;
    const bool bt = !isg;

    const int bm = blockIdx.y * BM, bn = blockIdx.x * BN;
    const int tid = threadIdx.x;
    const int lane = tid & 31, wid = tid >> 5;

    uint64_t acc2[4][8];
#pragma unroll
    for (int i = 0; i < 4; i++)
#pragma unroll
        for (int j = 0; j < 8; j++) acc2[i][j] = 0ull;

    const int ar = tid >> 2, ac = (tid & 3) * 4;
    float4 ra, rb0, rb1;
    auto ldg = [&](int k0){
        ra = *(const float4*)(A + (long)(bm + ar) * lda + k0 + ac);
        if (bt){
            rb0 = *(const float4*)(B + (long)(bn + ar) * ldb + k0 + ac);
            rb1 = *(const float4*)(B + (long)(bn + ar + 128) * ldb + k0 + ac);
        } else {
            const int bk = tid >> 6, bc = (tid & 63) * 4;
            rb0 = *(const float4*)(B + (long)(k0 + bk) * ldb + bn + bc);
            rb1 = *(const float4*)(B + (long)(k0 + bk + 8) * ldb + bn + bc);
        }
    };
    auto sts = [&](){
        As[ac + 0][ar] = ra.x; As[ac + 1][ar] = ra.y;
        As[ac + 2][ar] = ra.z; As[ac + 3][ar] = ra.w;
        if (bt){
            Bs[ac + 0][ar] = rb0.x; Bs[ac + 1][ar] = rb0.y;
            Bs[ac + 2][ar] = rb0.z; Bs[ac + 3][ar] = rb0.w;
            Bs[ac + 0][ar + 128] = rb1.x; Bs[ac + 1][ar + 128] = rb1.y;
            Bs[ac + 2][ar + 128] = rb1.z; Bs[ac + 3][ar + 128] = rb1.w;
        } else {
            const int bk = tid >> 6, bc = (tid & 63) * 4;
            *(float4*)&Bs[bk][bc]     = rb0;
            *(float4*)&Bs[bk + 8][bc] = rb1;
        }
    };

    const int nch = K / BK;
    ldg(0);
    for (int c = 0; c < nch; c++){
        sts();
        __syncthreads();
        if (c + 1 < nch) ldg((c + 1) * BK);
#pragma unroll
        for (int kk = 0; kk < BK; kk++){
            uint64_t a2[4];
#pragma unroll
            for (int i = 0; i < 4; i++)
                a2[i] = *(const uint64_t*)&As[kk][wid * 8 + 2 * i];
            float4 b40 = *(const float4*)&Bs[kk][lane * 4];
            float4 b41 = *(const float4*)&Bs[kk][128 + lane * 4];
            uint64_t b2[8] = {pack2(b40.x), pack2(b40.y), pack2(b40.z), pack2(b40.w),
                              pack2(b41.x), pack2(b41.y), pack2(b41.z), pack2(b41.w)};
#pragma unroll
            for (int i = 0; i < 4; i++)
#pragma unroll
                for (int j = 0; j < 8; j++)
                    ffma2(acc2[i][j], a2[i], b2[j]);
        }
        __syncthreads();
    }

#pragma unroll
    for (int i = 0; i < 4; i++){
#pragma unroll
        for (int h2 = 0; h2 < 2; h2++){
            const int r = bm + wid * 8 + i * 2 + h2;
#pragma unroll
            for (int grp = 0; grp < 2; grp++){
                const int col = bn + grp * 128 + lane * 4;
                float4 o; float* po = &o.x;
#pragma unroll
                for (int u = 0; u < 4; u++){
                    float2 p; memcpy(&p, &acc2[i][grp * 4 + u], 8);
                    float v = h2 ? p.y : p.x;
                    if (isg){ v += bs[col + u]; v = v / (1.0f + expf(-v)); }
                    po[u] = v;
                }
                *(float4*)(C + (long)r * ldc + col) = o;
            }
        }
    }
}

// ---------------- HMMA 2-split out-GEMM (verbatim) ----------------
__global__ __launch_bounds__(256, 1) void gemm_mma_out(
    const bf16* __restrict__ A0, const bf16* __restrict__ A1,
    const bf16* __restrict__ B0, const bf16* __restrict__ B1,
    const float* __restrict__ bias, float* __restrict__ C,
    int K, int lda, int ldb, int ldc)
{
    extern __shared__ char dsm[];
    const int tid = threadIdx.x, wid = tid >> 5, lane = tid & 31;
    const int wm = wid & 1, wn = wid >> 1;
    const int bm = blockIdx.y * 128, bn = blockIdx.x * 128;
    const bf16* As[2] = {A0, A1};
    const bf16* Bs[2] = {B0, B1};

    uint32_t sb = (smem_u32(dsm) + 1023u) & ~1023u;
    const int nch = K >> 6;

    auto load_tile = [&](uint32_t st, const bf16* g, int ld, int c0){
#pragma unroll
        for (int t = 0; t < 4; t++){
            int c = tid + t * 256, r = c >> 3, c8 = c & 7;
            cp16(st + (uint32_t)(r * 128) + (uint32_t)(((c8 ^ (r & 7)) * 16)),
                 g + (size_t)r * ld + c0 + c8 * 8);
        }
    };
    auto load_chunk = [&](int stage, int k0){
        uint32_t st = sb + stage * 65536u;
#pragma unroll
        for (int sp = 0; sp < 2; sp++) load_tile(st + sp * 16384, As[sp] + (size_t)bm * lda, lda, k0);
#pragma unroll
        for (int sp = 0; sp < 2; sp++) load_tile(st + (2 + sp) * 16384, Bs[sp] + (size_t)bn * ldb, ldb, k0);
        cp_commit();
    };

    float acc[4][4][4];
#pragma unroll
    for (int i = 0; i < 4; i++)
#pragma unroll
        for (int j = 0; j < 4; j++)
#pragma unroll
            for (int u = 0; u < 4; u++) acc[i][j][u] = 0.0f;

    const int lr = lane & 15, lk = lane >> 4;

    load_chunk(0, 0);
    for (int c = 0; c < nch; c++){
        const int s = c & 1;
        if (c + 1 < nch){ load_chunk((c + 1) & 1, (c + 1) << 6); cp_wait<1>(); }
        else cp_wait<0>();
        __syncthreads();

        const uint32_t stg = sb + s * 65536u;
#pragma unroll
        for (int ks = 0; ks < 4; ks++){
            const int kc = ks * 2 + lk;
            uint32_t af[2][4][4], bfr[2][2][4];
#pragma unroll
            for (int sp = 0; sp < 2; sp++)
#pragma unroll
                for (int i = 0; i < 4; i++){
                    int r = wm * 64 + i * 16 + lr;
                    ldsm4(af[sp][i], stg + sp * 16384 + (uint32_t)(r * 128) + (uint32_t)(((kc ^ (r & 7)) * 16)));
                }
#pragma unroll
            for (int sp = 0; sp < 2; sp++)
#pragma unroll
                for (int j2 = 0; j2 < 2; j2++){
                    int rn = wn * 32 + j2 * 16 + lr;
                    ldsm4(bfr[sp][j2], stg + (2 + sp) * 16384 + (uint32_t)(rn * 128) + (uint32_t)(((kc ^ (rn & 7)) * 16)));
                }
#pragma unroll
            for (int i = 0; i < 4; i++)
#pragma unroll
                for (int j2 = 0; j2 < 2; j2++){
                    mma16816(acc[i][2*j2],   af[0][i], bfr[0][j2][0], bfr[0][j2][2]);
                    mma16816(acc[i][2*j2+1], af[0][i], bfr[0][j2][1], bfr[0][j2][3]);
                    mma16816(acc[i][2*j2],   af[0][i], bfr[1][j2][0], bfr[1][j2][2]);
                    mma16816(acc[i][2*j2+1], af[0][i], bfr[1][j2][1], bfr[1][j2][3]);
                    mma16816(acc[i][2*j2],   af[1][i], bfr[0][j2][0], bfr[0][j2][2]);
                    mma16816(acc[i][2*j2+1], af[1][i], bfr[0][j2][1], bfr[0][j2][3]);
                }
        }
        __syncthreads();
    }

    const int tr = lane >> 2, tc = (lane & 3) * 2;
#pragma unroll
    for (int i = 0; i < 4; i++)
#pragma unroll
        for (int h2 = 0; h2 < 2; h2++){
            const int row = bm + wm * 64 + i * 16 + tr + h2 * 8;
#pragma unroll
            for (int j = 0; j < 4; j++){
                const int col = bn + wn * 32 + j * 8 + tc;
                float v0 = acc[i][j][h2*2] + bias[col];
                float v1 = acc[i][j][h2*2+1] + bias[col+1];
                *(float2*)(C + (size_t)row * ldc + col) = make_float2(v0, v1);
            }
        }
}

// ---------------- prep: Wv [K][N] -> wv2 splits [N][K] ----------------
__global__ void tsplit_kernel(const float* __restrict__ in,
    bf16* __restrict__ o0, bf16* __restrict__ o1, int K, int N)
{
    __shared__ float t[32][33];
    int k0 = blockIdx.y * 32, n0 = blockIdx.x * 32;
    t[threadIdx.y][threadIdx.x] = in[(size_t)(k0 + threadIdx.y) * N + n0 + threadIdx.x];
    __syncthreads();
    float v = t[threadIdx.x][threadIdx.y];
    size_t o = (size_t)(n0 + threadIdx.y) * K + k0 + threadIdx.x;
    bf16 h, l; split2v(v, h, l);
    o0[o] = h; o1[o] = l;
}

// ---------------- fused topk1(sorted-merge) + topk2 + gather ----------------
__constant__ unsigned short c_cand[128] = {
    0x000,0x001,0x002,0x003,0x004,0x005,0x006,0x007,0x008,0x009,0x00A,0x00B,0x00C,0x00D,0x00E,0x00F,
    0x010,0x011,0x012,0x013,0x014,0x015,0x016,0x017,0x018,0x019,0x01A,0x01B,0x01C,0x01D,0x01E,0x01F,
    0x100,0x101,0x102,0x103,0x104,0x105,0x106,0x107,0x108,0x109,0x10A,0x10B,0x10C,0x10D,0x10E,0x10F,
    0x200,0x201,0x202,0x203,0x204,0x205,0x206,0x207,0x208,0x209,
    0x300,0x301,0x302,0x303,0x304,0x305,0x306,0x307,
    0x400,0x401,0x402,0x403,0x404,0x405,
    0x500,0x501,0x502,0x503,0x504,
    0x600,0x601,0x602,0x603,
    0x700,0x701,0x702,0x703,
    0x800,0x801,0x802, 0x900,0x901,0x902,
    0xA00,0xA01, 0xB00,0xB01, 0xC00,0xC01, 0xD00,0xD01, 0xE00,0xE01, 0xF00,0xF01,
    0x1000,0x1100,0x1200,0x1300,0x1400,0x1500,0x1600,0x1700,
    0x1800,0x1900,0x1A00,0x1B00,0x1C00,0x1D00,0x1E00,0x1F00,
    0xFFFF,0xFFFF,0xFFFF,0xFFFF,0xFFFF,0xFFFF,0xFFFF,0xFFFF,0xFFFF };

__global__ __launch_bounds__(256) void topk_gather_kernel(const float* __restrict__ values)
{
    const int n = blockIdx.x;
    const int tid = threadIdx.x;
    const int wid = tid >> 5, lane = tid & 31;
    const unsigned FULL = 0xffffffffu;

    __shared__ float s_ts[8][32];
    __shared__ int   s_ti[8][32];
    __shared__ unsigned long long s_lists[8][16][32];
    __shared__ unsigned long long skeys[4][128];
    __shared__ float s_cw[128];
    __shared__ int   s_ci[128];

    // ---- stage 1: sorted 8-lists + 32-pop merge with REDUX argmax ----
    {
        const float* sc = g_scores + (size_t)n * 4096 + (size_t)wid * 512;
        unsigned long long kA[8], kB[8];
#pragma unroll
        for (int i = 0; i < 8; i++){
            float v = sc[i * 32 + lane];
            unsigned u = __float_as_uint(v);
            unsigned s = (u & 0x80000000u) ? ~u : (u | 0x80000000u);
            kA[i] = ((unsigned long long)s << 32) | (unsigned long long)(1023 - (i * 32 + lane));
        }
#pragma unroll
        for (int i = 0; i < 8; i++){
            float v = sc[(i + 8) * 32 + lane];
            unsigned u = __float_as_uint(v);
            unsigned s = (u & 0x80000000u) ? ~u : (u | 0x80000000u);
            kB[i] = ((unsigned long long)s << 32) | (unsigned long long)(1023 - ((i + 8) * 32 + lane));
        }
        sort8_desc(kA);
        sort8_desc(kB);
#pragma unroll
        for (int i = 0; i < 8; i++){
            s_lists[wid][i][lane]     = kA[i];
            s_lists[wid][8 + i][lane] = kB[i];
        }
        __syncwarp();

        int pA = 1, pB = 1;
        unsigned long long hA = kA[0], hB = kB[0];
        unsigned long long out = 0ull;
        for (int it = 0; it < 32; it++){
            unsigned long long h = (hA > hB) ? hA : hB;
            unsigned hi = (unsigned)(h >> 32);
            unsigned mhi = __reduce_max_sync(FULL, hi);
            unsigned lo = (hi == mhi) ? (unsigned)(h & 1023ull) : 0u;
            unsigned mlo = __reduce_max_sync(FULL, lo);
            unsigned long long m = ((unsigned long long)mhi << 32) | (unsigned long long)mlo;
            if (lane == it) out = m;
            if (h == m){
                if (hA == m){ hA = (pA < 8) ? s_lists[wid][pA][lane] : 0ull; pA++; }
                else        { hB = (pB < 8) ? s_lists[wid][8 + pB][lane] : 0ull; pB++; }
            }
        }
        unsigned sv = (unsigned)(out >> 32);
        unsigned ub = (sv & 0x80000000u) ? (sv & 0x7FFFFFFFu) : ~sv;
        s_ts[wid][lane] = __uint_as_float(ub);
        s_ti[wid][lane] = 1023 - (int)(out & 1023ull);
    }
    __syncthreads();

    // ---- stage 2: warps 0-3, dominance pruning + counting selection + softmax ----
    if (wid < 4){
        const int h = wid;
        float s1 = s_ts[h * 2][lane];
        float s2 = s_ts[h * 2 + 1][lane];

        float val[4]; unsigned long long key[4]; int ci_[4], cj_[4]; bool real[4];
#pragma unroll
        for (int s = 0; s < 4; s++){
            unsigned pk = c_cand[lane * 4 + s];
            int ci = (pk >> 8) & 31, cj = pk & 31;
            ci_[s] = ci; cj_[s] = cj;
            real[s] = (pk != 0xFFFFu);
            float v = __shfl_sync(FULL, s1, ci) + __shfl_sync(FULL, s2, cj);
            val[s] = v;
            unsigned u = __float_as_uint(v);
            unsigned sv = (u & 0x80000000u) ? ~u : (u | 0x80000000u);
            unsigned p = (unsigned)(ci * 32 + cj);
            key[s] = real[s] ? (((unsigned long long)sv << 32) | (unsigned long long)(1023u - p)) : 0ull;
            skeys[h][lane * 4 + s] = key[s];
        }
        __syncwarp();

        int cnt[4] = {0,0,0,0};
        for (int k2 = 0; k2 < 128; k2++){
            unsigned long long o = skeys[h][k2];
#pragma unroll
            for (int s = 0; s < 4; s++) cnt[s] += (o > key[s]);
        }
        bool sel[4];
#pragma unroll
        for (int s = 0; s < 4; s++) sel[s] = real[s] && (cnt[s] < 32);

        float m = -FLT_MAX;
#pragma unroll
        for (int s = 0; s < 4; s++) if (sel[s] && val[s] > m) m = val[s];
#pragma unroll
        for (int off = 16; off; off >>= 1) m = fmaxf(m, __shfl_xor_sync(FULL, m, off));
        float e[4], sum = 0.0f;
#pragma unroll
        for (int s = 0; s < 4; s++){ e[s] = sel[s] ? expf(val[s] - m) : 0.0f; sum += e[s]; }
#pragma unroll
        for (int off = 16; off; off >>= 1) sum += __shfl_xor_sync(FULL, sum, off);

#pragma unroll
        for (int s = 0; s < 4; s++){
            if (sel[s]){
                s_cw[h * 32 + cnt[s]] = e[s] / sum;
                s_ci[h * 32 + cnt[s]] = s_ti[h * 2][ci_[s]] * 512 + s_ti[h * 2 + 1][cj_[s]];
            }
        }
    }
    __syncthreads();

    // ---- gather: 256 threads, float2 over 512 dims, 4 indep chains (MLP x4) ----
    float2 a0 = {0.f,0.f}, a1 = {0.f,0.f}, a2c = {0.f,0.f}, a3 = {0.f,0.f};
#pragma unroll 2
    for (int r = 0; r < 128; r += 4){
        float w0 = s_cw[r],     w1 = s_cw[r + 1];
        float w2 = s_cw[r + 2], w3 = s_cw[r + 3];
        const float2 v0 = *((const float2*)(values + (size_t)s_ci[r]     * 512) + tid);
        const float2 v1 = *((const float2*)(values + (size_t)s_ci[r + 1] * 512) + tid);
        const float2 v2 = *((const float2*)(values + (size_t)s_ci[r + 2] * 512) + tid);
        const float2 v3 = *((const float2*)(values + (size_t)s_ci[r + 3] * 512) + tid);
        a0.x += w0 * v0.x; a0.y += w0 * v0.y;
        a1.x += w1 * v1.x; a1.y += w1 * v1.y;
        a2c.x += w2 * v2.x; a2c.y += w2 * v2.y;
        a3.x += w3 * v3.x; a3.y += w3 * v3.y;
    }
    float2 g = *((const float2*)(g_gate + (size_t)n * 512) + tid);
    float o0 = ((a0.x + a1.x) + (a2c.x + a3.x)) * g.x;
    float o1 = ((a0.y + a1.y) + (a2c.y + a3.y)) * g.y;
    bf16 h0,l0,h1,l1;
    split2v(o0,h0,l0); split2v(o1,h1,l1);
    *(uint32_t*)(&g_h2[0][(size_t)n * 512 + tid * 2]) =
        (uint32_t)__bfloat16_as_ushort(h0) | ((uint32_t)__bfloat16_as_ushort(h1) << 16);
    *(uint32_t*)(&g_h2[1][(size_t)n * 512 + tid * 2]) =
        (uint32_t)__bfloat16_as_ushort(l0) | ((uint32_t)__bfloat16_as_ushort(l1) << 16);
}

// ---------------- launch (single stream, R15 structure) ----------------
extern "C" void kernel_launch(void* const* d_in, const int* in_sizes, int n_in,
                              void* d_out, int out_size)
{
    const float* x      = (const float*)d_in[0];
    const float* Wq     = (const float*)d_in[1];
    const float* bq     = (const float*)d_in[2];
    const float* keys   = (const float*)d_in[3];
    const float* values = (const float*)d_in[4];
    const float* Ws     = (const float*)d_in[5];
    const float* bs     = (const float*)d_in[6];
    const float* Wv     = (const float*)d_in[7];
    const float* bv     = (const float*)d_in[8];
    float* out          = (float*)d_out;

    const int SMEM2 = 2 * 2 * 32768;
    cudaFuncSetAttribute(gemm_mma_out, cudaFuncAttributeMaxDynamicSharedMemorySize, SMEM2);

    float *q, *scores, *gate;
    bf16 *wv2[2], *h2[2];
    cudaGetSymbolAddress((void**)&q, g_q);
    cudaGetSymbolAddress((void**)&scores, g_scores);
    cudaGetSymbolAddress((void**)&gate, g_gate);
    {
        bf16* base;
        cudaGetSymbolAddress((void**)&base, g_wv2); for (int i=0;i<2;i++) wv2[i] = base + (size_t)i*1024*512;
        cudaGetSymbolAddress((void**)&base, g_h2);  for (int i=0;i<2;i++) h2[i]  = base + (size_t)i*2048*512;
    }

    // 1) q = x @ Wq + bq  (fp32, f32x2, exact)
    gemm_q<<<dim3(2048/256, 2048/128, 1), 512>>>(x, Wq, bq, q);

    // 2) gate (z=0, long blocks first) + scores (z=1..8) fused
    scores_gate_kernel<<<dim3(2, 16, 9), 512>>>(q, keys, x, Ws, bs, scores, gate);

    // 3) prep for out-GEMM
    tsplit_kernel<<<dim3(32, 16), dim3(32, 32)>>>(Wv, wv2[0], wv2[1], 512, 1024);

    // 4) topk1 + topk2 + gather fused (MLP x4 gather)
    topk_gather_kernel<<<2048, 256>>>(values);

    // 5) out = hidden @ Wv + bv  (HMMA 2-split)
    gemm_mma_out<<<dim3(8,16,1), 256, SMEM2>>>(
        h2[0], h2[1], wv2[0], wv2[1], bv, out, 512, 512, 512, 1024);
}